// round 4
// baseline (speedup 1.0000x reference)
#include <cuda_runtime.h>
#include <cuda_bf16.h>
#include <cstddef>
#include <cstdint>

// Problem constants
#define BB   4
#define CC   128
#define CR   32
#define HH   64
#define WW   64
#define HW   (HH * WW)          // 4096
#define KK   7
#define KK2  49
#define PAD  3

// Involution tile config
#define TW   32                 // tile width (pixels)
#define TH   16                 // tile height (pixels), 2 per thread
#define CG   32                 // channels per block -> grid = 128 = 1 wave
#define SMW  (TW + 2 * PAD)     // 38
#define SMH  (TH + 2 * PAD)     // 22
#define TILE_ELEMS (SMH * SMW)  // 836
#define XS_BYTES (CG * TILE_ELEMS * sizeof(float))  // 107008

// Scratch for generated kernel tensor [B][49][H*W]
__device__ float g_kern[BB * KK2 * HW];

// Packed f32x2 helpers (sm_103a)
__device__ __forceinline__ unsigned long long pack_f32x2(float lo, float hi) {
    unsigned long long r;
    asm("mov.b64 %0, {%1, %2};" : "=l"(r) : "f"(lo), "f"(hi));
    return r;
}
__device__ __forceinline__ unsigned long long fma_f32x2(unsigned long long a,
                                                        unsigned long long b,
                                                        unsigned long long c) {
    unsigned long long r;
    asm("fma.rn.f32x2 %0, %1, %2, %3;" : "=l"(r) : "l"(a), "l"(b), "l"(c));
    return r;
}
__device__ __forceinline__ void unpack_f32x2(unsigned long long v, float& lo, float& hi) {
    asm("mov.b64 {%0, %1}, %2;" : "=f"(lo), "=f"(hi) : "l"(v));
}

// ---------------------------------------------------------------------------
// Kernel 1: per-pixel kernel generation
//   f  = relu(BN(W1 @ x_px + b1))          (128 -> 32)
//   k  = W2 @ f + b2                        (32 -> 49)
// One thread per pixel. Weights staged in smem, w1 transposed to [c][32] so
// the inner loop is 1 coalesced LDG + 8x broadcast LDS.128 + 32 FFMA.
// ---------------------------------------------------------------------------
__global__ __launch_bounds__(128)
void gen_kernel(const float* __restrict__ x,
                const float* __restrict__ w1, const float* __restrict__ b1,
                const float* __restrict__ gamma, const float* __restrict__ beta,
                const float* __restrict__ mean,  const float* __restrict__ var,
                const float* __restrict__ w2,    const float* __restrict__ b2)
{
    __shared__ float w1s[CC * CR];     // [c][o]
    __shared__ float w2s[KK2 * CR];    // [ij][o]
    __shared__ float b2s[KK2];
    __shared__ float scs[CR], shs[CR], b1s[CR];

    const int tid = threadIdx.x;

    for (int i = tid; i < CC * CR; i += 128) {
        int o = i & (CR - 1);
        int c = i >> 5;
        w1s[i] = w1[o * CC + c];       // transpose: w1 given as [32][128]
    }
    for (int i = tid; i < KK2 * CR; i += 128) w2s[i] = w2[i];
    for (int i = tid; i < KK2; i += 128)      b2s[i] = b2[i];
    if (tid < CR) {
        float s = gamma[tid] * rsqrtf(var[tid] + 1e-5f);
        scs[tid] = s;
        shs[tid] = beta[tid] - mean[tid] * s;
        b1s[tid] = b1[tid];
    }
    __syncthreads();

    const int px = blockIdx.x * 128 + tid;    // 0..16383
    const int b  = px >> 12;
    const int hw = px & (HW - 1);
    const float* xp = x + (size_t)b * CC * HW + hw;

    float f[CR];
#pragma unroll
    for (int o = 0; o < CR; ++o) f[o] = 0.0f;

#pragma unroll 4
    for (int c = 0; c < CC; ++c) {
        float xv = __ldg(xp + c * HW);
        const float4* wr = (const float4*)(w1s + c * CR);
#pragma unroll
        for (int q = 0; q < 8; ++q) {
            float4 wv = wr[q];
            f[4 * q + 0] = fmaf(wv.x, xv, f[4 * q + 0]);
            f[4 * q + 1] = fmaf(wv.y, xv, f[4 * q + 1]);
            f[4 * q + 2] = fmaf(wv.z, xv, f[4 * q + 2]);
            f[4 * q + 3] = fmaf(wv.w, xv, f[4 * q + 3]);
        }
    }

#pragma unroll
    for (int o = 0; o < CR; ++o)
        f[o] = fmaxf(fmaf(f[o] + b1s[o], scs[o], shs[o]), 0.0f);

    float* kp = g_kern + (size_t)b * KK2 * HW + hw;
#pragma unroll 7
    for (int ij = 0; ij < KK2; ++ij) {
        float acc = b2s[ij];
        const float4* wr = (const float4*)(w2s + ij * CR);
#pragma unroll
        for (int q = 0; q < 8; ++q) {
            float4 wv = wr[q];
            acc = fmaf(wv.x, f[4 * q + 0], acc);
            acc = fmaf(wv.y, f[4 * q + 1], acc);
            acc = fmaf(wv.z, f[4 * q + 2], acc);
            acc = fmaf(wv.w, f[4 * q + 3], acc);
        }
        kp[ij * HW] = acc;
    }
}

// ---------------------------------------------------------------------------
// Kernel 2: involution gather.
// Block = 256 threads = 32x8 lanes; each thread owns pixels (h0+2ty, w0+tx)
// and (h0+2ty+1, w0+tx). The two pixels share every smem tap value: window
// row r feeds pixel0 with k0[r][j] and pixel1 with k1[r-1][j]. We therefore
// pack (k0[r][j], k1[r-1][j]) as f32x2 pairs in registers (edge rows zero-
// padded) and accumulate both pixels with one fma.rn.f32x2 per tap:
// 1 LDS.32 + 1 pack-mov (alu pipe) + 1 FFMA2 (fma pipe). The smem crossbar
// becomes the sole binding pipe; fma-pipe load is halved.
// Grid = 128 blocks = single wave on 148 SMs.
// ---------------------------------------------------------------------------
extern __shared__ float xs[];

__global__ __launch_bounds__(256)
void inv_kernel(const float* __restrict__ x, float* __restrict__ out)
{
    const int tid = threadIdx.x;
    const int tx  = tid & 31;
    const int ty  = tid >> 5;           // 0..7
    const int b   = blockIdx.z >> 2;    // z = b*(C/CG) + cg, C/CG = 4
    const int c0  = (blockIdx.z & 3) * CG;
    const int w0  = blockIdx.x * TW;
    const int h0  = blockIdx.y * TH;

    // Stage x tiles (with halo) for CG channels
    for (int c = 0; c < CG; ++c) {
        const float* xc = x + (size_t)(b * CC + c0 + c) * HW;
        float* xsc = xs + c * TILE_ELEMS;
        for (int i = tid; i < TILE_ELEMS; i += 256) {
            int r = i / SMW, q = i - r * SMW;
            int gh = h0 + r - PAD;
            int gw = w0 + q - PAD;
            float v = 0.0f;
            if (gh >= 0 && gh < HH && gw >= 0 && gw < WW)
                v = __ldg(xc + gh * WW + gw);
            xsc[i] = v;
        }
    }

    // Load per-pixel kernels (coalesced along w) and pack into f32x2 pairs:
    // kp[r][j] = ( k0[r*7+j] (row r valid for pixel0: r<7),
    //              k1[(r-1)*7+j] (valid for pixel1: r>0) ), zeros elsewhere.
    const int h = h0 + 2 * ty;
    const int w = w0 + tx;
    const float* kgp = g_kern + (size_t)b * KK2 * HW + h * WW + w;
    unsigned long long kp[(KK + 1) * KK];   // 8 rows x 7 cols packed
#pragma unroll
    for (int r = 0; r < KK + 1; ++r) {
#pragma unroll
        for (int j = 0; j < KK; ++j) {
            float klo = (r < KK) ? kgp[(r * KK + j) * HW]            : 0.0f;
            float khi = (r > 0)  ? kgp[((r - 1) * KK + j) * HW + WW] : 0.0f;
            kp[r * KK + j] = pack_f32x2(klo, khi);
        }
    }
    __syncthreads();

    float* op = out + (size_t)(b * CC + c0) * HW + h * WW + w;
    for (int c = 0; c < CG; ++c) {
        const float* xsc = xs + c * TILE_ELEMS + (2 * ty) * SMW + tx;
        unsigned long long acc = pack_f32x2(0.0f, 0.0f);
#pragma unroll
        for (int r = 0; r < KK + 1; ++r) {
#pragma unroll
            for (int j = 0; j < KK; ++j) {
                float v = xsc[r * SMW + j];
                acc = fma_f32x2(kp[r * KK + j], pack_f32x2(v, v), acc);
            }
        }
        float a0, a1;
        unpack_f32x2(acc, a0, a1);
        op[c * HW]      = a0;
        op[c * HW + WW] = a1;
    }
}

// ---------------------------------------------------------------------------
extern "C" void kernel_launch(void* const* d_in, const int* in_sizes, int n_in,
                              void* d_out, int out_size)
{
    const float* x     = (const float*)d_in[0];
    const float* w1    = (const float*)d_in[1];
    const float* b1    = (const float*)d_in[2];
    const float* gamma = (const float*)d_in[3];
    const float* beta  = (const float*)d_in[4];
    const float* mean  = (const float*)d_in[5];
    const float* var   = (const float*)d_in[6];
    const float* w2    = (const float*)d_in[7];
    const float* b2    = (const float*)d_in[8];
    float* out = (float*)d_out;

    cudaFuncSetAttribute(inv_kernel,
                         cudaFuncAttributeMaxDynamicSharedMemorySize,
                         (int)XS_BYTES);

    gen_kernel<<<16384 / 128, 128>>>(x, w1, b1, gamma, beta, mean, var, w2, b2);

    dim3 grid(WW / TW, HH / TH, BB * (CC / CG));   // (2, 4, 16) = 128 blocks
    inv_kernel<<<grid, 256, XS_BYTES>>>(x, out);
}

// round 5
// speedup vs baseline: 1.0464x; 1.0464x over previous
#include <cuda_runtime.h>
#include <cuda_bf16.h>
#include <cstddef>
#include <cstdint>

// Problem constants
#define BB   4
#define CC   128
#define CR   32
#define HH   64
#define WW   64
#define HW   (HH * WW)          // 4096
#define KK   7
#define KK2  49
#define PAD  3

// Involution tile config
#define TW   32                 // tile width (pixels)
#define TH   16                 // tile height (pixels), 2 per thread (vertical)
#define CG   16                 // channels per block -> grid = 256 blocks
#define SMW  (TW + 2 * PAD)     // 38
#define SMH  (TH + 2 * PAD)     // 22
#define TILE_ELEMS (SMH * SMW)  // 836
#define XS_BYTES (CG * TILE_ELEMS * sizeof(float))  // 53504

// Scratch for generated kernel tensor [B][49][H*W]
__device__ float g_kern[BB * KK2 * HW];

// Packed f32x2 helpers (sm_103a)
__device__ __forceinline__ unsigned long long pack_f32x2(float lo, float hi) {
    unsigned long long r;
    asm("mov.b64 %0, {%1, %2};" : "=l"(r) : "f"(lo), "f"(hi));
    return r;
}
__device__ __forceinline__ unsigned long long fma_f32x2(unsigned long long a,
                                                        unsigned long long b,
                                                        unsigned long long c) {
    unsigned long long r;
    asm("fma.rn.f32x2 %0, %1, %2, %3;" : "=l"(r) : "l"(a), "l"(b), "l"(c));
    return r;
}
__device__ __forceinline__ void unpack_f32x2(unsigned long long v, float& lo, float& hi) {
    asm("mov.b64 {%0, %1}, %2;" : "=f"(lo), "=f"(hi) : "l"(v));
}

// ---------------------------------------------------------------------------
// Kernel 1: per-pixel kernel generation (measured ~6us, at its FFMA floor)
//   f  = relu(BN(W1 @ x_px + b1))          (128 -> 32)
//   k  = W2 @ f + b2                        (32 -> 49)
// ---------------------------------------------------------------------------
__global__ __launch_bounds__(128)
void gen_kernel(const float* __restrict__ x,
                const float* __restrict__ w1, const float* __restrict__ b1,
                const float* __restrict__ gamma, const float* __restrict__ beta,
                const float* __restrict__ mean,  const float* __restrict__ var,
                const float* __restrict__ w2,    const float* __restrict__ b2)
{
    __shared__ float w1s[CC * CR];     // [c][o]
    __shared__ float w2s[KK2 * CR];    // [ij][o]
    __shared__ float b2s[KK2];
    __shared__ float scs[CR], shs[CR], b1s[CR];

    const int tid = threadIdx.x;

    for (int i = tid; i < CC * CR; i += 128) {
        int o = i & (CR - 1);
        int c = i >> 5;
        w1s[i] = w1[o * CC + c];       // transpose: w1 given as [32][128]
    }
    for (int i = tid; i < KK2 * CR; i += 128) w2s[i] = w2[i];
    for (int i = tid; i < KK2; i += 128)      b2s[i] = b2[i];
    if (tid < CR) {
        float s = gamma[tid] * rsqrtf(var[tid] + 1e-5f);
        scs[tid] = s;
        shs[tid] = beta[tid] - mean[tid] * s;
        b1s[tid] = b1[tid];
    }
    __syncthreads();

    const int px = blockIdx.x * 128 + tid;    // 0..16383
    const int b  = px >> 12;
    const int hw = px & (HW - 1);
    const float* xp = x + (size_t)b * CC * HW + hw;

    float f[CR];
#pragma unroll
    for (int o = 0; o < CR; ++o) f[o] = 0.0f;

#pragma unroll 4
    for (int c = 0; c < CC; ++c) {
        float xv = __ldg(xp + c * HW);
        const float4* wr = (const float4*)(w1s + c * CR);
#pragma unroll
        for (int q = 0; q < 8; ++q) {
            float4 wv = wr[q];
            f[4 * q + 0] = fmaf(wv.x, xv, f[4 * q + 0]);
            f[4 * q + 1] = fmaf(wv.y, xv, f[4 * q + 1]);
            f[4 * q + 2] = fmaf(wv.z, xv, f[4 * q + 2]);
            f[4 * q + 3] = fmaf(wv.w, xv, f[4 * q + 3]);
        }
    }

#pragma unroll
    for (int o = 0; o < CR; ++o)
        f[o] = fmaxf(fmaf(f[o] + b1s[o], scs[o], shs[o]), 0.0f);

    float* kp = g_kern + (size_t)b * KK2 * HW + hw;
#pragma unroll 7
    for (int ij = 0; ij < KK2; ++ij) {
        float acc = b2s[ij];
        const float4* wr = (const float4*)(w2s + ij * CR);
#pragma unroll
        for (int q = 0; q < 8; ++q) {
            float4 wv = wr[q];
            acc = fmaf(wv.x, f[4 * q + 0], acc);
            acc = fmaf(wv.y, f[4 * q + 1], acc);
            acc = fmaf(wv.z, f[4 * q + 2], acc);
            acc = fmaf(wv.w, f[4 * q + 3], acc);
        }
        kp[ij * HW] = acc;
    }
}

// ---------------------------------------------------------------------------
// Kernel 2: involution gather — LOOP-INTERCHANGED.
// Block = 256 threads = 32x8; each thread owns 2 vertically-adjacent pixels.
// Outer loops: window row r (0..7), tap col j (0..6).
//   - load the 2 k-taps for this (r,j) from gmem (L2-resident, predicated
//     at the r=0 / r=7 edges), pack as f32x2.
//   - inner loop over CG=16 channels: 1 LDS + 1 pack + 1 FFMA2 into the
//     per-channel packed accumulator -> 16 INDEPENDENT dependency chains.
// Registers: 16 packed accumulators (32 regs) + misc ~ 60 total -> 3 blocks/SM
// (24 warps), no spills. Crossbar is the binding pipe (~14k cyc/SM).
// ---------------------------------------------------------------------------
extern __shared__ float xs[];

__global__ __launch_bounds__(256, 3)
void inv_kernel(const float* __restrict__ x, float* __restrict__ out)
{
    const int tid = threadIdx.x;
    const int tx  = tid & 31;
    const int ty  = tid >> 5;           // 0..7
    const int b   = blockIdx.z >> 3;    // z = b*(C/CG) + cg, C/CG = 8
    const int c0  = (blockIdx.z & 7) * CG;
    const int w0  = blockIdx.x * TW;
    const int h0  = blockIdx.y * TH;

    // Stage x tiles (with halo) for CG channels
    for (int c = 0; c < CG; ++c) {
        const float* xc = x + (size_t)(b * CC + c0 + c) * HW;
        float* xsc = xs + c * TILE_ELEMS;
        for (int i = tid; i < TILE_ELEMS; i += 256) {
            int r = i / SMW, q = i - r * SMW;
            int gh = h0 + r - PAD;
            int gw = w0 + q - PAD;
            float v = 0.0f;
            if (gh >= 0 && gh < HH && gw >= 0 && gw < WW)
                v = __ldg(xc + gh * WW + gw);
            xsc[i] = v;
        }
    }

    const int h = h0 + 2 * ty;
    const int w = w0 + tx;
    const float* kgp = g_kern + (size_t)b * KK2 * HW + h * WW + w;

    __syncthreads();

    // Per-channel packed accumulators: lane0 = pixel (h, w), lane1 = (h+1, w)
    unsigned long long acc[CG];
#pragma unroll
    for (int c = 0; c < CG; ++c) acc[c] = 0ULL;

    const float* xbase = xs + (2 * ty) * SMW + tx;

    for (int r = 0; r < KK + 1; ++r) {        // 8 window rows per thread
#pragma unroll
        for (int j = 0; j < KK; ++j) {
            // k-taps for this window row: pixel0 uses tap row r (valid r<7),
            // pixel1 uses tap row r-1 (valid r>0).
            float klo = 0.0f, khi = 0.0f;
            if (r < KK) klo = __ldg(kgp + (r * KK + j) * HW);
            if (r > 0)  khi = __ldg(kgp + ((r - 1) * KK + j) * HW + WW);
            unsigned long long kp = pack_f32x2(klo, khi);

#pragma unroll
            for (int c = 0; c < CG; ++c) {
                float v = xbase[c * TILE_ELEMS + r * SMW + j];
                acc[c] = fma_f32x2(kp, pack_f32x2(v, v), acc[c]);
            }
        }
    }

    float* op = out + (size_t)(b * CC + c0) * HW + h * WW + w;
#pragma unroll
    for (int c = 0; c < CG; ++c) {
        float a0, a1;
        unpack_f32x2(acc[c], a0, a1);
        op[c * HW]      = a0;
        op[c * HW + WW] = a1;
    }
}

// ---------------------------------------------------------------------------
extern "C" void kernel_launch(void* const* d_in, const int* in_sizes, int n_in,
                              void* d_out, int out_size)
{
    const float* x     = (const float*)d_in[0];
    const float* w1    = (const float*)d_in[1];
    const float* b1    = (const float*)d_in[2];
    const float* gamma = (const float*)d_in[3];
    const float* beta  = (const float*)d_in[4];
    const float* mean  = (const float*)d_in[5];
    const float* var   = (const float*)d_in[6];
    const float* w2    = (const float*)d_in[7];
    const float* b2    = (const float*)d_in[8];
    float* out = (float*)d_out;

    cudaFuncSetAttribute(inv_kernel,
                         cudaFuncAttributeMaxDynamicSharedMemorySize,
                         (int)XS_BYTES);

    gen_kernel<<<16384 / 128, 128>>>(x, w1, b1, gamma, beta, mean, var, w2, b2);

    dim3 grid(WW / TW, HH / TH, BB * (CC / CG));   // (2, 4, 32) = 256 blocks
    inv_kernel<<<grid, 256, XS_BYTES>>>(x, out);
}

// round 6
// speedup vs baseline: 1.2433x; 1.1882x over previous
#include <cuda_runtime.h>
#include <cuda_bf16.h>
#include <cstddef>
#include <cstdint>

// Problem constants
#define BB   4
#define CC   128
#define CR   32
#define HH   64
#define WW   64
#define HW   (HH * WW)          // 4096
#define KK   7
#define KK2  49
#define PAD  3

// Involution tile config
#define TW   32                 // tile width (pixels)
#define TH   16                 // tile height (pixels), 2 per thread (vertical)
#define CG   8                  // channels per block -> grid = 512 blocks
#define SMW  (TW + 2 * PAD)     // 38
#define SMH  (TH + 2 * PAD)     // 22
#define TILE_ELEMS (SMH * SMW)  // 836
#define XS_BYTES (CG * TILE_ELEMS * sizeof(float))  // 26752

// Scratch for generated kernel tensor [B][49][H*W]
__device__ float g_kern[BB * KK2 * HW];

// Packed f32x2 helpers (sm_103a)
__device__ __forceinline__ unsigned long long pack_f32x2(float lo, float hi) {
    unsigned long long r;
    asm("mov.b64 %0, {%1, %2};" : "=l"(r) : "f"(lo), "f"(hi));
    return r;
}
__device__ __forceinline__ unsigned long long fma_f32x2(unsigned long long a,
                                                        unsigned long long b,
                                                        unsigned long long c) {
    unsigned long long r;
    asm("fma.rn.f32x2 %0, %1, %2, %3;" : "=l"(r) : "l"(a), "l"(b), "l"(c));
    return r;
}
__device__ __forceinline__ void unpack_f32x2(unsigned long long v, float& lo, float& hi) {
    asm("mov.b64 {%0, %1}, %2;" : "=f"(lo), "=f"(hi) : "l"(v));
}

// ---------------------------------------------------------------------------
// Kernel 1: per-pixel kernel generation (measured ~6us, near its FFMA floor)
// ---------------------------------------------------------------------------
__global__ __launch_bounds__(128)
void gen_kernel(const float* __restrict__ x,
                const float* __restrict__ w1, const float* __restrict__ b1,
                const float* __restrict__ gamma, const float* __restrict__ beta,
                const float* __restrict__ mean,  const float* __restrict__ var,
                const float* __restrict__ w2,    const float* __restrict__ b2)
{
    __shared__ float w1s[CC * CR];     // [c][o]
    __shared__ float w2s[KK2 * CR];    // [ij][o]
    __shared__ float b2s[KK2];
    __shared__ float scs[CR], shs[CR], b1s[CR];

    const int tid = threadIdx.x;

    for (int i = tid; i < CC * CR; i += 128) {
        int o = i & (CR - 1);
        int c = i >> 5;
        w1s[i] = w1[o * CC + c];       // transpose: w1 given as [32][128]
    }
    for (int i = tid; i < KK2 * CR; i += 128) w2s[i] = w2[i];
    for (int i = tid; i < KK2; i += 128)      b2s[i] = b2[i];
    if (tid < CR) {
        float s = gamma[tid] * rsqrtf(var[tid] + 1e-5f);
        scs[tid] = s;
        shs[tid] = beta[tid] - mean[tid] * s;
        b1s[tid] = b1[tid];
    }
    __syncthreads();

    const int px = blockIdx.x * 128 + tid;    // 0..16383
    const int b  = px >> 12;
    const int hw = px & (HW - 1);
    const float* xp = x + (size_t)b * CC * HW + hw;

    float f[CR];
#pragma unroll
    for (int o = 0; o < CR; ++o) f[o] = 0.0f;

#pragma unroll 4
    for (int c = 0; c < CC; ++c) {
        float xv = __ldg(xp + c * HW);
        const float4* wr = (const float4*)(w1s + c * CR);
#pragma unroll
        for (int q = 0; q < 8; ++q) {
            float4 wv = wr[q];
            f[4 * q + 0] = fmaf(wv.x, xv, f[4 * q + 0]);
            f[4 * q + 1] = fmaf(wv.y, xv, f[4 * q + 1]);
            f[4 * q + 2] = fmaf(wv.z, xv, f[4 * q + 2]);
            f[4 * q + 3] = fmaf(wv.w, xv, f[4 * q + 3]);
        }
    }

#pragma unroll
    for (int o = 0; o < CR; ++o)
        f[o] = fmaxf(fmaf(f[o] + b1s[o], scs[o], shs[o]), 0.0f);

    float* kp = g_kern + (size_t)b * KK2 * HW + hw;
#pragma unroll 7
    for (int ij = 0; ij < KK2; ++ij) {
        float acc = b2s[ij];
        const float4* wr = (const float4*)(w2s + ij * CR);
#pragma unroll
        for (int q = 0; q < 8; ++q) {
            float4 wv = wr[q];
            acc = fmaf(wv.x, f[4 * q + 0], acc);
            acc = fmaf(wv.y, f[4 * q + 1], acc);
            acc = fmaf(wv.z, f[4 * q + 2], acc);
            acc = fmaf(wv.w, f[4 * q + 3], acc);
        }
        kp[ij * HW] = acc;
    }
}

// ---------------------------------------------------------------------------
// Kernel 2: involution gather — prefetch-pipelined k-taps + high occupancy.
// Block = 256 threads = 32x8; each thread owns 2 vertically-adjacent pixels.
// CG=8 channels/block -> 512 blocks -> ~3.5 blocks/SM (occ ~43%).
// For window row r, the 14 k-taps for row r+1 are prefetched into a second
// register buffer while row r computes: 8 channels x 7 taps of
// {LDS + pack + FFMA2} (~170 instrs) hide the ~250-cyc L2-hit LDG latency.
// ---------------------------------------------------------------------------
extern __shared__ float xs[];

__global__ __launch_bounds__(256, 3)
void inv_kernel(const float* __restrict__ x, float* __restrict__ out)
{
    const int tid = threadIdx.x;
    const int tx  = tid & 31;
    const int ty  = tid >> 5;           // 0..7
    const int b   = blockIdx.z >> 4;    // z = b*(C/CG) + cg, C/CG = 16
    const int c0  = (blockIdx.z & 15) * CG;
    const int w0  = blockIdx.x * TW;
    const int h0  = blockIdx.y * TH;

    // Stage x tiles (with halo) for CG channels
    for (int c = 0; c < CG; ++c) {
        const float* xc = x + (size_t)(b * CC + c0 + c) * HW;
        float* xsc = xs + c * TILE_ELEMS;
        for (int i = tid; i < TILE_ELEMS; i += 256) {
            int r = i / SMW, q = i - r * SMW;
            int gh = h0 + r - PAD;
            int gw = w0 + q - PAD;
            float v = 0.0f;
            if (gh >= 0 && gh < HH && gw >= 0 && gw < WW)
                v = __ldg(xc + gh * WW + gw);
            xsc[i] = v;
        }
    }

    const int h = h0 + 2 * ty;
    const int w = w0 + tx;
    const float* kgp = g_kern + (size_t)b * KK2 * HW + h * WW + w;

    // Per-channel packed accumulators: lane0 = pixel (h,w), lane1 = (h+1,w)
    unsigned long long acc[CG];
#pragma unroll
    for (int c = 0; c < CG; ++c) acc[c] = 0ULL;

    // Preload taps for window row 0: pixel0 uses tap row 0, pixel1 none.
    float cur_lo[KK], cur_hi[KK];
#pragma unroll
    for (int j = 0; j < KK; ++j) {
        cur_lo[j] = __ldg(kgp + j * HW);
        cur_hi[j] = 0.0f;
    }

    __syncthreads();

    const float* xbase = xs + (2 * ty) * SMW + tx;

#pragma unroll
    for (int r = 0; r < KK + 1; ++r) {        // 8 window rows per thread
        // Prefetch taps for window row r+1:
        //   pixel0 tap row r+1 (valid r+1 < 7), pixel1 tap row r (valid r < 7)
        float nxt_lo[KK], nxt_hi[KK];
        if (r < KK) {
#pragma unroll
            for (int j = 0; j < KK; ++j) {
                nxt_lo[j] = (r + 1 < KK) ? __ldg(kgp + ((r + 1) * KK + j) * HW) : 0.0f;
                nxt_hi[j] = __ldg(kgp + (r * KK + j) * HW + WW);
            }
        }

        // Compute window row r with current taps
#pragma unroll
        for (int j = 0; j < KK; ++j) {
            unsigned long long kp = pack_f32x2(cur_lo[j], cur_hi[j]);
#pragma unroll
            for (int c = 0; c < CG; ++c) {
                float v = xbase[c * TILE_ELEMS + r * SMW + j];
                acc[c] = fma_f32x2(kp, pack_f32x2(v, v), acc[c]);
            }
        }

        if (r < KK) {
#pragma unroll
            for (int j = 0; j < KK; ++j) {
                cur_lo[j] = nxt_lo[j];
                cur_hi[j] = nxt_hi[j];
            }
        }
    }

    float* op = out + (size_t)(b * CC + c0) * HW + h * WW + w;
#pragma unroll
    for (int c = 0; c < CG; ++c) {
        float a0, a1;
        unpack_f32x2(acc[c], a0, a1);
        op[c * HW]      = a0;
        op[c * HW + WW] = a1;
    }
}

// ---------------------------------------------------------------------------
extern "C" void kernel_launch(void* const* d_in, const int* in_sizes, int n_in,
                              void* d_out, int out_size)
{
    const float* x     = (const float*)d_in[0];
    const float* w1    = (const float*)d_in[1];
    const float* b1    = (const float*)d_in[2];
    const float* gamma = (const float*)d_in[3];
    const float* beta  = (const float*)d_in[4];
    const float* mean  = (const float*)d_in[5];
    const float* var   = (const float*)d_in[6];
    const float* w2    = (const float*)d_in[7];
    const float* b2    = (const float*)d_in[8];
    float* out = (float*)d_out;

    cudaFuncSetAttribute(inv_kernel,
                         cudaFuncAttributeMaxDynamicSharedMemorySize,
                         (int)XS_BYTES);

    gen_kernel<<<16384 / 128, 128>>>(x, w1, b1, gamma, beta, mean, var, w2, b2);

    dim3 grid(WW / TW, HH / TH, BB * (CC / CG));   // (2, 4, 64) = 512 blocks
    inv_kernel<<<grid, 256, XS_BYTES>>>(x, out);
}

// round 7
// speedup vs baseline: 1.4111x; 1.1349x over previous
#include <cuda_runtime.h>
#include <cuda_bf16.h>
#include <cstddef>
#include <cstdint>

// Problem constants
#define BB   4
#define CC   128
#define CR   32
#define HH   64
#define WW   64
#define HW   (HH * WW)          // 4096
#define KK   7
#define KK2  49
#define PAD  3

// Involution tile config
#define TW   32                 // tile width (pixels)
#define TH   16                 // tile height (pixels), 2 per thread (vertical)
#define CG   8                  // channels per block -> grid = 512 blocks
#define SMW  (TW + 2 * PAD)     // 38
#define SMH  (TH + 2 * PAD)     // 22
#define TILE_ELEMS (SMH * SMW)  // 836
// duplicated float2 tiles: 8 bytes per element
#define XS_BYTES (CG * TILE_ELEMS * sizeof(float2))  // 53504

// Scratch for generated kernel tensor [B][49][H*W]
__device__ float g_kern[BB * KK2 * HW];

// Packed f32x2 helpers (sm_103a)
__device__ __forceinline__ unsigned long long pack_f32x2(float lo, float hi) {
    unsigned long long r;
    asm("mov.b64 %0, {%1, %2};" : "=l"(r) : "f"(lo), "f"(hi));
    return r;
}
__device__ __forceinline__ unsigned long long fma_f32x2(unsigned long long a,
                                                        unsigned long long b,
                                                        unsigned long long c) {
    unsigned long long r;
    asm("fma.rn.f32x2 %0, %1, %2, %3;" : "=l"(r) : "l"(a), "l"(b), "l"(c));
    return r;
}
__device__ __forceinline__ void unpack_f32x2(unsigned long long v, float& lo, float& hi) {
    asm("mov.b64 {%0, %1}, %2;" : "=f"(lo), "=f"(hi) : "l"(v));
}

// ---------------------------------------------------------------------------
// Kernel 1: per-pixel kernel generation — 2-way channel split-K.
// 256 threads/block, 128 pixels/block. Threads (px, half) for half in {0,1}
// each accumulate 64 channels into f[32]; partials reduced through smem
// (transposed [o][px] layout -> conflict-free), BN+ReLU applied once, then
// the 49 outputs are split 24/25 between the two halves.
// ---------------------------------------------------------------------------
__global__ __launch_bounds__(256)
void gen_kernel(const float* __restrict__ x,
                const float* __restrict__ w1, const float* __restrict__ b1,
                const float* __restrict__ gamma, const float* __restrict__ beta,
                const float* __restrict__ mean,  const float* __restrict__ var,
                const float* __restrict__ w2,    const float* __restrict__ b2)
{
    __shared__ float w1s[CC * CR];       // [c][o]
    __shared__ float w2s[KK2 * CR];      // [ij][o]
    __shared__ float b2s[KK2];
    __shared__ float scs[CR], shs[CR], b1s[CR];
    __shared__ float fred[CR][128];      // transposed partial/final f

    const int tid  = threadIdx.x;
    const int pxl  = tid & 127;          // pixel slot within block
    const int half = tid >> 7;           // channel half 0/1

    for (int i = tid; i < CC * CR; i += 256) {
        int o = i & (CR - 1);
        int c = i >> 5;
        w1s[i] = w1[o * CC + c];         // transpose: w1 given as [32][128]
    }
    for (int i = tid; i < KK2 * CR; i += 256) w2s[i] = w2[i];
    for (int i = tid; i < KK2; i += 256)      b2s[i] = b2[i];
    if (tid < CR) {
        float s = gamma[tid] * rsqrtf(var[tid] + 1e-5f);
        scs[tid] = s;
        shs[tid] = beta[tid] - mean[tid] * s;
        b1s[tid] = b1[tid];
    }
    __syncthreads();

    const int px = blockIdx.x * 128 + pxl;    // 0..16383
    const int b  = px >> 12;
    const int hw = px & (HW - 1);
    const float* xp = x + (size_t)b * CC * HW + hw + (size_t)half * 64 * HW;

    float f[CR];
#pragma unroll
    for (int o = 0; o < CR; ++o) f[o] = 0.0f;

#pragma unroll 4
    for (int c = 0; c < 64; ++c) {            // this half's 64 channels
        float xv = __ldg(xp + c * HW);
        const float4* wr = (const float4*)(w1s + (half * 64 + c) * CR);
#pragma unroll
        for (int q = 0; q < 8; ++q) {
            float4 wv = wr[q];
            f[4 * q + 0] = fmaf(wv.x, xv, f[4 * q + 0]);
            f[4 * q + 1] = fmaf(wv.y, xv, f[4 * q + 1]);
            f[4 * q + 2] = fmaf(wv.z, xv, f[4 * q + 2]);
            f[4 * q + 3] = fmaf(wv.w, xv, f[4 * q + 3]);
        }
    }

    // Reduce the two halves through smem, apply bias+BN+ReLU once (half 1).
    if (half == 0) {
#pragma unroll
        for (int o = 0; o < CR; ++o) fred[o][pxl] = f[o];
    }
    __syncthreads();
    if (half == 1) {
#pragma unroll
        for (int o = 0; o < CR; ++o) {
            float v = f[o] + fred[o][pxl];
            fred[o][pxl] = fmaxf(fmaf(v + b1s[o], scs[o], shs[o]), 0.0f);
        }
    }
    __syncthreads();

    // Reload final f into registers (conflict-free: lanes read consecutive px)
#pragma unroll
    for (int o = 0; o < CR; ++o) f[o] = fred[o][pxl];

    // Split the 49 outputs: half 0 -> ij 0..23, half 1 -> ij 24..48
    const int ij0 = half ? 24 : 0;
    const int ijn = half ? 25 : 24;
    float* kp = g_kern + (size_t)b * KK2 * HW + hw;
#pragma unroll 5
    for (int t = 0; t < ijn; ++t) {
        int ij = ij0 + t;
        float acc = b2s[ij];
        const float4* wr = (const float4*)(w2s + ij * CR);
#pragma unroll
        for (int q = 0; q < 8; ++q) {
            float4 wv = wr[q];
            acc = fmaf(wv.x, f[4 * q + 0], acc);
            acc = fmaf(wv.y, f[4 * q + 1], acc);
            acc = fmaf(wv.z, f[4 * q + 2], acc);
            acc = fmaf(wv.w, f[4 * q + 3], acc);
        }
        kp[ij * HW] = acc;
    }
}

// ---------------------------------------------------------------------------
// Kernel 2: involution gather — duplicated-smem f32x2 + 4 blocks/SM.
// Block = 256 threads = 32x8; each thread owns 2 vertically-adjacent pixels.
// x values staged as (v,v) float2 so the inner step is 1 LDS.64 + 1 FFMA2
// (no pack). k taps packed (pixel0 row r, pixel1 row r-1) per window row;
// full unroll lets ptxas hoist the tap LDGs (L2-resident) for MLP.
// ---------------------------------------------------------------------------
extern __shared__ float2 xs2[];

__global__ __launch_bounds__(256, 4)
void inv_kernel(const float* __restrict__ x, float* __restrict__ out)
{
    const int tid = threadIdx.x;
    const int tx  = tid & 31;
    const int ty  = tid >> 5;           // 0..7
    const int b   = blockIdx.z >> 4;    // z = b*(C/CG) + cg, C/CG = 16
    const int c0  = (blockIdx.z & 15) * CG;
    const int w0  = blockIdx.x * TW;
    const int h0  = blockIdx.y * TH;

    // Stage x tiles (with halo) for CG channels, duplicated as (v,v)
    for (int c = 0; c < CG; ++c) {
        const float* xc = x + (size_t)(b * CC + c0 + c) * HW;
        float2* xsc = xs2 + c * TILE_ELEMS;
        for (int i = tid; i < TILE_ELEMS; i += 256) {
            int r = i / SMW, q = i - r * SMW;
            int gh = h0 + r - PAD;
            int gw = w0 + q - PAD;
            float v = 0.0f;
            if (gh >= 0 && gh < HH && gw >= 0 && gw < WW)
                v = __ldg(xc + gh * WW + gw);
            xsc[i] = make_float2(v, v);
        }
    }

    const int h = h0 + 2 * ty;
    const int w = w0 + tx;
    const float* kgp = g_kern + (size_t)b * KK2 * HW + h * WW + w;

    // Per-channel packed accumulators: lane0 = pixel (h,w), lane1 = (h+1,w)
    unsigned long long acc[CG];
#pragma unroll
    for (int c = 0; c < CG; ++c) acc[c] = 0ULL;

    __syncthreads();

    const unsigned long long* xbase =
        (const unsigned long long*)xs2 + (2 * ty) * SMW + tx;

#pragma unroll
    for (int r = 0; r < KK + 1; ++r) {        // 8 window rows per thread
        // k taps for this window row: pixel0 tap row r (valid r<7),
        // pixel1 tap row r-1 (valid r>0). Edges zero-padded.
        float klo[KK], khi[KK];
#pragma unroll
        for (int j = 0; j < KK; ++j) {
            klo[j] = (r < KK) ? __ldg(kgp + (r * KK + j) * HW)            : 0.0f;
            khi[j] = (r > 0)  ? __ldg(kgp + ((r - 1) * KK + j) * HW + WW) : 0.0f;
        }
#pragma unroll
        for (int j = 0; j < KK; ++j) {
            unsigned long long kp = pack_f32x2(klo[j], khi[j]);
#pragma unroll
            for (int c = 0; c < CG; ++c) {
                unsigned long long v2 = xbase[c * TILE_ELEMS + r * SMW + j];
                acc[c] = fma_f32x2(kp, v2, acc[c]);
            }
        }
    }

    float* op = out + (size_t)(b * CC + c0) * HW + h * WW + w;
#pragma unroll
    for (int c = 0; c < CG; ++c) {
        float a0, a1;
        unpack_f32x2(acc[c], a0, a1);
        op[c * HW]      = a0;
        op[c * HW + WW] = a1;
    }
}

// ---------------------------------------------------------------------------
extern "C" void kernel_launch(void* const* d_in, const int* in_sizes, int n_in,
                              void* d_out, int out_size)
{
    const float* x     = (const float*)d_in[0];
    const float* w1    = (const float*)d_in[1];
    const float* b1    = (const float*)d_in[2];
    const float* gamma = (const float*)d_in[3];
    const float* beta  = (const float*)d_in[4];
    const float* mean  = (const float*)d_in[5];
    const float* var   = (const float*)d_in[6];
    const float* w2    = (const float*)d_in[7];
    const float* b2    = (const float*)d_in[8];
    float* out = (float*)d_out;

    cudaFuncSetAttribute(inv_kernel,
                         cudaFuncAttributeMaxDynamicSharedMemorySize,
                         (int)XS_BYTES);

    gen_kernel<<<16384 / 128, 256>>>(x, w1, b1, gamma, beta, mean, var, w2, b2);

    dim3 grid(WW / TW, HH / TH, BB * (CC / CG));   // (2, 4, 64) = 512 blocks
    inv_kernel<<<grid, 256, XS_BYTES>>>(x, out);
}

// round 16
// speedup vs baseline: 1.7400x; 1.2331x over previous
#include <cuda_runtime.h>
#include <cuda_bf16.h>
#include <cstddef>
#include <cstdint>

// Problem constants
#define BB   4
#define CC   128
#define CR   32
#define HH   64
#define WW   64
#define HW   (HH * WW)          // 4096
#define KK   7
#define KK2  49
#define PAD  3

// Involution tile config
#define TW   32                 // tile width (pixels)
#define TH   16                 // tile height (pixels), 2 per thread (vertical)
#define CG   4                  // channels per block -> grid = 1024 blocks
#define SMW  (TW + 2 * PAD)     // 38
#define SMH  (TH + 2 * PAD)     // 22
#define TILE_ELEMS (SMH * SMW)  // 836
// duplicated float2 tiles: 8 bytes per element
#define XS_BYTES (CG * TILE_ELEMS * sizeof(float2))  // 26752

// Scratch for generated kernel tensor [B][49][H*W]
__device__ float g_kern[BB * KK2 * HW];

// Packed f32x2 helpers (sm_103a)
__device__ __forceinline__ unsigned long long pack_f32x2(float lo, float hi) {
    unsigned long long r;
    asm("mov.b64 %0, {%1, %2};" : "=l"(r) : "f"(lo), "f"(hi));
    return r;
}
__device__ __forceinline__ unsigned long long fma_f32x2(unsigned long long a,
                                                        unsigned long long b,
                                                        unsigned long long c) {
    unsigned long long r;
    asm("fma.rn.f32x2 %0, %1, %2, %3;" : "=l"(r) : "l"(a), "l"(b), "l"(c));
    return r;
}
__device__ __forceinline__ void unpack_f32x2(unsigned long long v, float& lo, float& hi) {
    asm("mov.b64 {%0, %1}, %2;" : "=f"(lo), "=f"(hi) : "l"(v));
}

// ---------------------------------------------------------------------------
// Kernel 1: per-pixel kernel generation — 2-way channel split-K, FULL UNROLL.
// 256 threads/block, 128 pixels/block. Each half accumulates 64 channels;
// the 64-iteration channel loop is fully unrolled so ptxas front-batches the
// x LDGs (MLP ~40-64) -> one exposed memory stall instead of sixteen.
// ---------------------------------------------------------------------------
__global__ __launch_bounds__(256)
void gen_kernel(const float* __restrict__ x,
                const float* __restrict__ w1, const float* __restrict__ b1,
                const float* __restrict__ gamma, const float* __restrict__ beta,
                const float* __restrict__ mean,  const float* __restrict__ var,
                const float* __restrict__ w2,    const float* __restrict__ b2)
{
    __shared__ float w1s[CC * CR];       // [c][o]
    __shared__ float w2s[KK2 * CR];      // [ij][o]
    __shared__ float b2s[KK2];
    __shared__ float scs[CR], shs[CR], b1s[CR];
    __shared__ float fred[CR][128];      // transposed partial/final f

    const int tid  = threadIdx.x;
    const int pxl  = tid & 127;          // pixel slot within block
    const int half = tid >> 7;           // channel half 0/1

    for (int i = tid; i < CC * CR; i += 256) {
        int o = i & (CR - 1);
        int c = i >> 5;
        w1s[i] = w1[o * CC + c];         // transpose: w1 given as [32][128]
    }
    for (int i = tid; i < KK2 * CR; i += 256) w2s[i] = w2[i];
    for (int i = tid; i < KK2; i += 256)      b2s[i] = b2[i];
    if (tid < CR) {
        float s = gamma[tid] * rsqrtf(var[tid] + 1e-5f);
        scs[tid] = s;
        shs[tid] = beta[tid] - mean[tid] * s;
        b1s[tid] = b1[tid];
    }
    __syncthreads();

    const int px = blockIdx.x * 128 + pxl;    // 0..16383
    const int b  = px >> 12;
    const int hw = px & (HW - 1);
    const float* xp = x + (size_t)b * CC * HW + hw + (size_t)half * 64 * HW;

    float f[CR];
#pragma unroll
    for (int o = 0; o < CR; ++o) f[o] = 0.0f;

#pragma unroll
    for (int c = 0; c < 64; ++c) {            // this half's 64 channels
        float xv = __ldg(xp + c * HW);
        const float4* wr = (const float4*)(w1s + (half * 64 + c) * CR);
#pragma unroll
        for (int q = 0; q < 8; ++q) {
            float4 wv = wr[q];
            f[4 * q + 0] = fmaf(wv.x, xv, f[4 * q + 0]);
            f[4 * q + 1] = fmaf(wv.y, xv, f[4 * q + 1]);
            f[4 * q + 2] = fmaf(wv.z, xv, f[4 * q + 2]);
            f[4 * q + 3] = fmaf(wv.w, xv, f[4 * q + 3]);
        }
    }

    // Reduce the two halves through smem, apply bias+BN+ReLU once (half 1).
    if (half == 0) {
#pragma unroll
        for (int o = 0; o < CR; ++o) fred[o][pxl] = f[o];
    }
    __syncthreads();
    if (half == 1) {
#pragma unroll
        for (int o = 0; o < CR; ++o) {
            float v = f[o] + fred[o][pxl];
            fred[o][pxl] = fmaxf(fmaf(v + b1s[o], scs[o], shs[o]), 0.0f);
        }
    }
    __syncthreads();

    // Reload final f into registers (conflict-free: lanes read consecutive px)
#pragma unroll
    for (int o = 0; o < CR; ++o) f[o] = fred[o][pxl];

    // Split the 49 outputs: half 0 -> ij 0..23, half 1 -> ij 24..48
    const int ij0 = half ? 24 : 0;
    const int ijn = half ? 25 : 24;
    float* kp = g_kern + (size_t)b * KK2 * HW + hw;
#pragma unroll
    for (int t = 0; t < 25; ++t) {
        if (t >= ijn) break;
        int ij = ij0 + t;
        float acc = b2s[ij];
        const float4* wr = (const float4*)(w2s + ij * CR);
#pragma unroll
        for (int q = 0; q < 8; ++q) {
            float4 wv = wr[q];
            acc = fmaf(wv.x, f[4 * q + 0], acc);
            acc = fmaf(wv.y, f[4 * q + 1], acc);
            acc = fmaf(wv.z, f[4 * q + 2], acc);
            acc = fmaf(wv.w, f[4 * q + 3], acc);
        }
        kp[ij * HW] = acc;
    }
}

// ---------------------------------------------------------------------------
// Kernel 2: involution gather — duplicated-smem f32x2, HIGH OCCUPANCY.
// CG=4 channels/block -> 1024 blocks, 26.8 KB smem, reg target 51 via
// __launch_bounds__(256,5) -> up to 40 warps/SM. Each thread owns 2
// vertically-adjacent pixels; inner step is 1 LDS.64 + 1 FFMA2.
// Taps for each window row are packed immediately (kp2[7], 14 regs) to
// minimize live registers under the reg cap.
// ---------------------------------------------------------------------------
extern __shared__ float2 xs2[];

__global__ __launch_bounds__(256, 5)
void inv_kernel(const float* __restrict__ x, float* __restrict__ out)
{
    const int tid = threadIdx.x;
    const int tx  = tid & 31;
    const int ty  = tid >> 5;           // 0..7
    const int b   = blockIdx.z >> 5;    // z = b*(C/CG) + cg, C/CG = 32
    const int c0  = (blockIdx.z & 31) * CG;
    const int w0  = blockIdx.x * TW;
    const int h0  = blockIdx.y * TH;

    // Stage x tiles (with halo): element-outer, channel-inner.
    {
        const float* xc0 = x + (size_t)(b * CC + c0) * HW;
        for (int i = tid; i < TILE_ELEMS; i += 256) {
            int r = i / SMW, q = i - r * SMW;
            int gh = h0 + r - PAD;
            int gw = w0 + q - PAD;
            bool valid = (gh >= 0) & (gh < HH) & (gw >= 0) & (gw < WW);
            int off = gh * WW + gw;
#pragma unroll
            for (int c = 0; c < CG; ++c) {
                float v = valid ? __ldg(xc0 + c * HW + off) : 0.0f;
                xs2[c * TILE_ELEMS + i] = make_float2(v, v);
            }
        }
    }

    const int h = h0 + 2 * ty;
    const int w = w0 + tx;
    const float* kgp = g_kern + (size_t)b * KK2 * HW + h * WW + w;

    // Per-channel packed accumulators: lane0 = pixel (h,w), lane1 = (h+1,w)
    unsigned long long acc[CG];
#pragma unroll
    for (int c = 0; c < CG; ++c) acc[c] = 0ULL;

    __syncthreads();

    const unsigned long long* xbase =
        (const unsigned long long*)xs2 + (2 * ty) * SMW + tx;

#pragma unroll
    for (int r = 0; r < KK + 1; ++r) {        // 8 window rows per thread
        // k taps for this window row, packed immediately:
        // lane0 = pixel0 tap row r (valid r<7), lane1 = pixel1 tap row r-1
        // (valid r>0). Edges zero-padded.
        unsigned long long kp2[KK];
#pragma unroll
        for (int j = 0; j < KK; ++j) {
            float klo = (r < KK) ? __ldg(kgp + (r * KK + j) * HW)            : 0.0f;
            float khi = (r > 0)  ? __ldg(kgp + ((r - 1) * KK + j) * HW + WW) : 0.0f;
            kp2[j] = pack_f32x2(klo, khi);
        }
#pragma unroll
        for (int j = 0; j < KK; ++j) {
#pragma unroll
            for (int c = 0; c < CG; ++c) {
                unsigned long long v2 = xbase[c * TILE_ELEMS + r * SMW + j];
                acc[c] = fma_f32x2(kp2[j], v2, acc[c]);
            }
        }
    }

    float* op = out + (size_t)(b * CC + c0) * HW + h * WW + w;
#pragma unroll
    for (int c = 0; c < CG; ++c) {
        float a0, a1;
        unpack_f32x2(acc[c], a0, a1);
        op[c * HW]      = a0;
        op[c * HW + WW] = a1;
    }
}

// ---------------------------------------------------------------------------
extern "C" void kernel_launch(void* const* d_in, const int* in_sizes, int n_in,
                              void* d_out, int out_size)
{
    const float* x     = (const float*)d_in[0];
    const float* w1    = (const float*)d_in[1];
    const float* b1    = (const float*)d_in[2];
    const float* gamma = (const float*)d_in[3];
    const float* beta  = (const float*)d_in[4];
    const float* mean  = (const float*)d_in[5];
    const float* var   = (const float*)d_in[6];
    const float* w2    = (const float*)d_in[7];
    const float* b2    = (const float*)d_in[8];
    float* out = (float*)d_out;

    cudaFuncSetAttribute(inv_kernel,
                         cudaFuncAttributeMaxDynamicSharedMemorySize,
                         (int)XS_BYTES);

    gen_kernel<<<16384 / 128, 256>>>(x, w1, b1, gamma, beta, mean, var, w2, b2);

    dim3 grid(WW / TW, HH / TH, BB * (CC / CG));   // (2, 4, 128) = 1024 blocks
    inv_kernel<<<grid, 256, XS_BYTES>>>(x, out);
}